// round 12
// baseline (speedup 1.0000x reference)
#include <cuda_runtime.h>
#include <cstdint>
#include <math.h>

#define BATCH   4
#define NNODES  4096
#define DIM     64
#define TM      64
#define KT      32
#define KSPLIT  4
#define KLEN    (NNODES / KSPLIT)     // 1024
#define NTL     (KLEN / KT)           // 32
#define THREADS 128
#define TOTE    (BATCH * NNODES * DIM)
#define NLAYER  3

// ---------------- scratch ----------------
__device__ float g_deg[BATCH * NNODES];
__device__ int   g_rowG2[BATCH * NNODES];                      // sum of G2 per row
__device__ unsigned char g_Ah[(size_t)BATCH * NNODES * NNODES]; // G2>>8 (u8), 67MB
__device__ unsigned char g_Al[(size_t)BATCH * NNODES * NNODES]; // (G2&255)-128 (s8)
__device__ unsigned char g_zTh[(size_t)BATCH * DIM * NNODES];   // zq>>8 (s8), transposed
__device__ unsigned char g_zTl[(size_t)BATCH * DIM * NNODES];   // (zq&255)-128 (s8)
__device__ float g_zfA[TOTE];
__device__ float g_zfB[TOTE];
__device__ __align__(16) float g_part[KSPLIT][TOTE];
__device__ float g_h1[TOTE], g_h2[TOTE], g_h3[TOTE];
__device__ unsigned int g_zmaxbits[NLAYER + 1];
__device__ int g_colzq[NLAYER][BATCH][DIM];

// ---------------- helpers ----------------
__device__ __forceinline__ void cp_async16(void* smem_dst, const void* gmem_src) {
    unsigned s = (unsigned)__cvta_generic_to_shared(smem_dst);
    asm volatile("cp.async.cg.shared.global [%0], [%1], 16;\n" :: "r"(s), "l"(gmem_src));
}
__device__ __forceinline__ void cp_commit() { asm volatile("cp.async.commit_group;\n"); }
template<int NREM>
__device__ __forceinline__ void cp_wait() {
    asm volatile("cp.async.wait_group %0;\n" :: "n"(NREM));
}
__device__ __forceinline__ void imma_u8s8(int* c, const uint32_t* a, const uint32_t* b) {
    asm volatile(
        "mma.sync.aligned.m16n8k32.row.col.s32.u8.s8.s32 "
        "{%0,%1,%2,%3}, {%4,%5,%6,%7}, {%8,%9}, {%0,%1,%2,%3};"
        : "+r"(c[0]), "+r"(c[1]), "+r"(c[2]), "+r"(c[3])
        : "r"(a[0]), "r"(a[1]), "r"(a[2]), "r"(a[3]), "r"(b[0]), "r"(b[1]));
}
__device__ __forceinline__ void imma_s8s8(int* c, const uint32_t* a, const uint32_t* b) {
    asm volatile(
        "mma.sync.aligned.m16n8k32.row.col.s32.s8.s8.s32 "
        "{%0,%1,%2,%3}, {%4,%5,%6,%7}, {%8,%9}, {%0,%1,%2,%3};"
        : "+r"(c[0]), "+r"(c[1]), "+r"(c[2]), "+r"(c[3])
        : "r"(a[0]), "r"(a[1]), "r"(a[2]), "r"(a[3]), "r"(b[0]), "r"(b[1]));
}

// ---------------- 0) init: zero maxes + colsums ----------------
__global__ void init_kernel() {
    int t = threadIdx.x;
    if (t < NLAYER + 1) g_zmaxbits[t] = 0u;
    int* c = &g_colzq[0][0][0];
    for (int i = t; i < NLAYER * BATCH * DIM; i += 256) c[i] = 0;
}

// ---------------- 1) prep: degrees + G -> int8 planes + row sums (G read once) --
__global__ void prep_kernel(const float* __restrict__ graph) {
    const int row = blockIdx.x;                          // b*N + i
    const float4* src = (const float4*)(graph + (size_t)row * NNODES);
    uint32_t* dH = (uint32_t*)(g_Ah + (size_t)row * NNODES);
    uint32_t* dL = (uint32_t*)(g_Al + (size_t)row * NNODES);
    float sf = 0.f;
    int   si = 0;
    #pragma unroll
    for (int u = 0; u < NNODES / 4 / 256; u++) {
        const int idx = threadIdx.x + u * 256;
        float4 v = src[idx];
        sf += (v.x + v.y) + (v.z + v.w);
        uint32_t q0 = min(65535u, __float2uint_rn(v.x * 65536.f));
        uint32_t q1 = min(65535u, __float2uint_rn(v.y * 65536.f));
        uint32_t q2 = min(65535u, __float2uint_rn(v.z * 65536.f));
        uint32_t q3 = min(65535u, __float2uint_rn(v.w * 65536.f));
        si += (int)(q0 + q1 + q2 + q3);
        dH[idx] = (q0 >> 8) | ((q1 >> 8) << 8) | ((q2 >> 8) << 16) | ((q3 >> 8) << 24);
        dL[idx] = ((q0 & 255u) ^ 128u) | (((q1 & 255u) ^ 128u) << 8)
                | (((q2 & 255u) ^ 128u) << 16) | (((q3 & 255u) ^ 128u) << 24);
    }
    #pragma unroll
    for (int o = 16; o > 0; o >>= 1) {
        sf += __shfl_down_sync(0xffffffffu, sf, o);
        si += __shfl_down_sync(0xffffffffu, si, o);
    }
    __shared__ float rf[8];
    __shared__ int   ri[8];
    if ((threadIdx.x & 31) == 0) { rf[threadIdx.x >> 5] = sf; ri[threadIdx.x >> 5] = si; }
    __syncthreads();
    if (threadIdx.x == 0) {
        float tot = 1.0f; int ti = 0;
        #pragma unroll
        for (int w = 0; w < 8; w++) { tot += rf[w]; ti += ri[w]; }
        g_deg[row]   = 1.0f / (sqrtf(tot) + 1e-7f);
        g_rowG2[row] = ti;
    }
}

// ---------------- 2) z0 = D*x (f32) + running max ----------------
__global__ void scale0_kernel(const float* __restrict__ x) {
    const int i = blockIdx.x * 256 + threadIdx.x;        // f4 index
    float4 v = ((const float4*)x)[i];
    const float d = g_deg[i >> 4];
    float4 z = make_float4(v.x * d, v.y * d, v.z * d, v.w * d);
    ((float4*)g_zfA)[i] = z;
    float m = fmaxf(fmaxf(fabsf(z.x), fabsf(z.y)), fmaxf(fabsf(z.z), fabsf(z.w)));
    #pragma unroll
    for (int o = 16; o > 0; o >>= 1) m = fmaxf(m, __shfl_down_sync(0xffffffffu, m, o));
    __shared__ float rm[8];
    if ((threadIdx.x & 31) == 0) rm[threadIdx.x >> 5] = m;
    __syncthreads();
    if (threadIdx.x == 0) {
        float bm = rm[0];
        #pragma unroll
        for (int w = 1; w < 8; w++) bm = fmaxf(bm, rm[w]);
        atomicMax(&g_zmaxbits[0], __float_as_uint(bm));
    }
}

// ---------------- 3) quantize+transpose z -> int8 planes + colsums ----------------
__global__ void quantT_kernel(const float* __restrict__ zf, int layer) {
    __shared__ float tile[64][65];
    const int b = blockIdx.y, k0 = blockIdx.x * 64;
    const int tid = threadIdx.x;
    const float* Z = zf + (size_t)b * NNODES * DIM;
    {
        int r  = tid >> 2;
        int c0 = (tid & 3) * 16;
        #pragma unroll
        for (int j = 0; j < 4; j++) {
            float4 v = *(const float4*)&Z[(size_t)(k0 + r) * DIM + c0 + j * 4];
            tile[r][c0 + j * 4 + 0] = v.x;
            tile[r][c0 + j * 4 + 1] = v.y;
            tile[r][c0 + j * 4 + 2] = v.z;
            tile[r][c0 + j * 4 + 3] = v.w;
        }
    }
    __syncthreads();
    const float zm = __uint_as_float(g_zmaxbits[layer]);
    const float rs = zm > 0.f ? 32700.f / zm : 0.f;
    {
        const int n  = tid >> 2;
        const int kq = (tid & 3) * 16;
        int csum = 0;
        uint32_t hw[4], lw[4];
        #pragma unroll
        for (int j = 0; j < 4; j++) {
            uint32_t hword = 0, lword = 0;
            #pragma unroll
            for (int bb = 0; bb < 4; bb++) {
                int k = kq + j * 4 + bb;
                int q = __float2int_rn(tile[k][n] * rs);
                csum += q;
                hword |= (((uint32_t)(q >> 8)) & 255u) << (8 * bb);
                lword |= ((((uint32_t)q & 255u)) ^ 128u) << (8 * bb);
            }
            hw[j] = hword; lw[j] = lword;
        }
        size_t base = ((size_t)(b * DIM + n)) * NNODES + k0 + kq;
        #pragma unroll
        for (int j = 0; j < 4; j++) {
            *(uint32_t*)(g_zTh + base + j * 4) = hw[j];
            *(uint32_t*)(g_zTl + base + j * 4) = lw[j];
        }
        csum += __shfl_down_sync(0xffffffffu, csum, 2);
        csum += __shfl_down_sync(0xffffffffu, csum, 1);
        if ((tid & 3) == 0) atomicAdd(&g_colzq[layer][b][n], csum);
    }
}

// ---------------- 4) propagation partial GEMM (int8, 3 planes) ----------------
__global__ void __launch_bounds__(THREADS)
prop_kernel() {
    __shared__ __align__(16) unsigned char sAh[2][TM][48];
    __shared__ __align__(16) unsigned char sAl[2][TM][48];
    __shared__ __align__(16) unsigned char sBh[2][DIM][48];
    __shared__ __align__(16) unsigned char sBl[2][DIM][48];

    const int tid  = threadIdx.x;
    const int lane = tid & 31;
    const int wid  = tid >> 5;
    const int wm   = (wid >> 1) * 32;
    const int wn   = (wid & 1) * 32;
    const int r    = lane >> 2;
    const int kq4  = (lane & 3) * 4;

    const int b = blockIdx.z;
    const int rowBase = blockIdx.x * TM;
    const int slice = blockIdx.y;
    const size_t kbase = (size_t)slice * KLEN;
    const unsigned char* Ah = g_Ah + ((size_t)(b * NNODES + rowBase)) * NNODES;
    const unsigned char* Al = g_Al + ((size_t)(b * NNODES + rowBase)) * NNODES;
    const unsigned char* Th = g_zTh + (size_t)b * DIM * NNODES;
    const unsigned char* Tl = g_zTl + (size_t)b * DIM * NNODES;

    int acc_hh[2][4][4], acc_mid[2][4][4];
    #pragma unroll
    for (int i = 0; i < 2; i++)
        #pragma unroll
        for (int j = 0; j < 4; j++)
            #pragma unroll
            for (int k = 0; k < 4; k++) { acc_hh[i][j][k] = 0; acc_mid[i][j][k] = 0; }

    auto issue = [&](int t, int st) {
        const size_t k0 = kbase + (size_t)t * KT;
        const int m = tid >> 1, half = tid & 1;
        cp_async16(&sAh[st][m][half * 16], Ah + (size_t)m * NNODES + k0 + half * 16);
        cp_async16(&sAl[st][m][half * 16], Al + (size_t)m * NNODES + k0 + half * 16);
        cp_async16(&sBh[st][m][half * 16], Th + (size_t)m * NNODES + k0 + half * 16);
        cp_async16(&sBl[st][m][half * 16], Tl + (size_t)m * NNODES + k0 + half * 16);
        cp_commit();
    };

    issue(0, 0);
    issue(1, 1);

    for (int t = 0; t < NTL; t++) {
        const int st = t & 1;
        if (t + 1 < NTL) cp_wait<1>(); else cp_wait<0>();
        __syncthreads();

        uint32_t ah[2][4], al[2][4];
        #pragma unroll
        for (int mb = 0; mb < 2; mb++) {
            const int m0 = wm + mb * 16 + r;
            ah[mb][0] = *(const uint32_t*)&sAh[st][m0    ][kq4];
            ah[mb][1] = *(const uint32_t*)&sAh[st][m0 + 8][kq4];
            ah[mb][2] = *(const uint32_t*)&sAh[st][m0    ][kq4 + 16];
            ah[mb][3] = *(const uint32_t*)&sAh[st][m0 + 8][kq4 + 16];
            al[mb][0] = *(const uint32_t*)&sAl[st][m0    ][kq4];
            al[mb][1] = *(const uint32_t*)&sAl[st][m0 + 8][kq4];
            al[mb][2] = *(const uint32_t*)&sAl[st][m0    ][kq4 + 16];
            al[mb][3] = *(const uint32_t*)&sAl[st][m0 + 8][kq4 + 16];
        }
        uint32_t bh[4][2], bl[4][2];
        #pragma unroll
        for (int nb = 0; nb < 4; nb++) {
            const int n = wn + nb * 8 + r;
            bh[nb][0] = *(const uint32_t*)&sBh[st][n][kq4];
            bh[nb][1] = *(const uint32_t*)&sBh[st][n][kq4 + 16];
            bl[nb][0] = *(const uint32_t*)&sBl[st][n][kq4];
            bl[nb][1] = *(const uint32_t*)&sBl[st][n][kq4 + 16];
        }
        #pragma unroll
        for (int mb = 0; mb < 2; mb++)
            #pragma unroll
            for (int nb = 0; nb < 4; nb++) {
                imma_u8s8(acc_hh [mb][nb], ah[mb], bh[nb]);
                imma_u8s8(acc_mid[mb][nb], ah[mb], bl[nb]);
                imma_s8s8(acc_mid[mb][nb], al[mb], bh[nb]);
            }
        __syncthreads();
        if (t + 2 < NTL) issue(t + 2, st);
    }

    // write partial (int units): P = 65536*S_hh + 256*S_mid
    float* P = g_part[slice] + (size_t)b * NNODES * DIM;
    #pragma unroll
    for (int mb = 0; mb < 2; mb++) {
        const int r0 = rowBase + wm + mb * 16 + r;
        const int r1 = r0 + 8;
        #pragma unroll
        for (int nb = 0; nb < 4; nb++) {
            const int c = wn + nb * 8 + 2 * (lane & 3);
            float p0 = (float)((double)acc_hh[mb][nb][0] * 65536.0 + (double)acc_mid[mb][nb][0] * 256.0);
            float p1 = (float)((double)acc_hh[mb][nb][1] * 65536.0 + (double)acc_mid[mb][nb][1] * 256.0);
            float p2 = (float)((double)acc_hh[mb][nb][2] * 65536.0 + (double)acc_mid[mb][nb][2] * 256.0);
            float p3 = (float)((double)acc_hh[mb][nb][3] * 65536.0 + (double)acc_mid[mb][nb][3] * 256.0);
            *(float2*)&P[(size_t)r0 * DIM + c] = make_float2(p0, p1);
            *(float2*)&P[(size_t)r1 * DIM + c] = make_float2(p2, p3);
        }
    }
}

// ---------------- 5) combine: h = d*(scale*(S+corr) + z_prev); z_next; max -----
__global__ void combine_kernel(const float* __restrict__ zfIn,
                               float* __restrict__ hOut, float* __restrict__ zfOut,
                               int layer) {
    const int i = blockIdx.x * 256 + threadIdx.x;        // f4 index
    const int node = i >> 4;
    const int b = node >> 12;
    const int n4 = (i & 15) * 4;
    const float d = g_deg[node];

    float4 s = ((const float4*)g_part[0])[i];
    #pragma unroll
    for (int p = 1; p < KSPLIT; p++) {
        float4 sp = ((const float4*)g_part[p])[i];
        s.x += sp.x; s.y += sp.y; s.z += sp.z; s.w += sp.w;
    }

    const float zm = __uint_as_float(g_zmaxbits[layer]);
    const float sc = zm > 0.f ? (zm / 32700.f) * (1.f / 65536.f) : 0.f;
    const float rg = (float)g_rowG2[node];
    int4 cq = *(const int4*)&g_colzq[layer][b][n4];
    const float CK = 16384.f * 4096.f;
    float c0 = 128.f * (rg + (float)cq.x) - CK;
    float c1 = 128.f * (rg + (float)cq.y) - CK;
    float c2 = 128.f * (rg + (float)cq.z) - CK;
    float c3 = 128.f * (rg + (float)cq.w) - CK;

    float4 zp = ((const float4*)zfIn)[i];
    float4 h;
    h.x = d * (sc * (s.x + c0) + zp.x);
    h.y = d * (sc * (s.y + c1) + zp.y);
    h.z = d * (sc * (s.z + c2) + zp.z);
    h.w = d * (sc * (s.w + c3) + zp.w);
    ((float4*)hOut)[i] = h;

    float4 zn = make_float4(d * h.x, d * h.y, d * h.z, d * h.w);
    ((float4*)zfOut)[i] = zn;

    float m = fmaxf(fmaxf(fabsf(zn.x), fabsf(zn.y)), fmaxf(fabsf(zn.z), fabsf(zn.w)));
    #pragma unroll
    for (int o = 16; o > 0; o >>= 1) m = fmaxf(m, __shfl_down_sync(0xffffffffu, m, o));
    __shared__ float rm[8];
    if ((threadIdx.x & 31) == 0) rm[threadIdx.x >> 5] = m;
    __syncthreads();
    if (threadIdx.x == 0) {
        float bm = rm[0];
        #pragma unroll
        for (int w = 1; w < 8; w++) bm = fmaxf(bm, rm[w]);
        atomicMax(&g_zmaxbits[layer + 1], __float_as_uint(bm));
    }
}

// ---------------- 6) out = concat(x,h1,h2,h3) @ W^T + b ----------------
__global__ void __launch_bounds__(256)
out_gemm_kernel(const float* __restrict__ x,
                const float* __restrict__ W,
                const float* __restrict__ bias,
                float* __restrict__ out)
{
    __shared__ float catS[16][256];
    __shared__ float Wt[64][65];

    const int tid = threadIdx.x;
    const int rowBase = blockIdx.x * 16;

    const float* srcs[4] = { x, g_h1, g_h2, g_h3 };
    {
        int r = tid >> 4, f4 = tid & 15;
        #pragma unroll
        for (int s = 0; s < 4; s++) {
            float4 v = *(const float4*)&srcs[s][(size_t)(rowBase + r) * DIM + f4 * 4];
            *(float4*)&catS[r][s * 64 + f4 * 4] = v;
        }
    }

    const int o  = tid & 63;
    const int rg = tid >> 6;

    float acc[4];
    {
        float bv = bias[o];
        #pragma unroll
        for (int j = 0; j < 4; j++) acc[j] = bv;
    }

    for (int fc = 0; fc < 4; fc++) {
        __syncthreads();
        #pragma unroll
        for (int u = 0; u < 4; u++) {
            int i  = tid + u * 256;
            int ro = i >> 4;
            int f4 = i & 15;
            float4 v = *(const float4*)&W[(size_t)ro * 256 + fc * 64 + f4 * 4];
            Wt[f4 * 4 + 0][ro] = v.x;
            Wt[f4 * 4 + 1][ro] = v.y;
            Wt[f4 * 4 + 2][ro] = v.z;
            Wt[f4 * 4 + 3][ro] = v.w;
        }
        __syncthreads();
        #pragma unroll
        for (int fl = 0; fl < 64; fl++) {
            float w = Wt[fl][o];
            #pragma unroll
            for (int j = 0; j < 4; j++)
                acc[j] += catS[rg * 4 + j][fc * 64 + fl] * w;
        }
    }

    #pragma unroll
    for (int j = 0; j < 4; j++)
        out[(size_t)(rowBase + rg * 4 + j) * DIM + o] = acc[j];
}

// ---------------- launch ----------------
template<typename T>
static T* symAddr(const T& symbol) {
    void* p = nullptr;
    cudaGetSymbolAddress(&p, symbol);
    return (T*)p;
}

extern "C" void kernel_launch(void* const* d_in, const int* in_sizes, int n_in,
                              void* d_out, int out_size) {
    const float* x     = (const float*)d_in[0];
    const float* graph = (const float*)d_in[1];
    const float* W     = (const float*)d_in[2];
    const float* bias  = (const float*)d_in[3];
    float* out = (float*)d_out;

    float* zfA = (float*)symAddr(g_zfA);
    float* zfB = (float*)symAddr(g_zfB);
    float* h1  = (float*)symAddr(g_h1);
    float* h2  = (float*)symAddr(g_h2);
    float* h3  = (float*)symAddr(g_h3);

    init_kernel<<<1, 256>>>();
    prep_kernel<<<BATCH * NNODES, 256>>>(graph);
    scale0_kernel<<<TOTE / 4 / 256, 256>>>(x);

    const dim3 qg(NNODES / 64, BATCH);
    const dim3 pg(NNODES / TM, KSPLIT, BATCH);
    const int cb = TOTE / 4 / 256;

    quantT_kernel<<<qg, 256>>>(zfA, 0);
    prop_kernel<<<pg, THREADS>>>();
    combine_kernel<<<cb, 256>>>(zfA, h1, zfB, 0);

    quantT_kernel<<<qg, 256>>>(zfB, 1);
    prop_kernel<<<pg, THREADS>>>();
    combine_kernel<<<cb, 256>>>(zfB, h2, zfA, 1);

    quantT_kernel<<<qg, 256>>>(zfA, 2);
    prop_kernel<<<pg, THREADS>>>();
    combine_kernel<<<cb, 256>>>(zfA, h3, zfB, 2);

    out_gemm_kernel<<<(BATCH * NNODES) / 16, 256>>>(x, W, bias, out);
}

// round 13
// speedup vs baseline: 1.0007x; 1.0007x over previous
#include <cuda_runtime.h>
#include <cstdint>
#include <math.h>

#define BATCH   4
#define NNODES  4096
#define DIM     64
#define TM      64
#define KT      32
#define KSPLIT  4
#define KLEN    (NNODES / KSPLIT)     // 1024
#define NTL     (KLEN / KT)           // 32
#define THREADS 128
#define TOTE    (BATCH * NNODES * DIM)
#define NLAYER  3

// ---------------- scratch ----------------
__device__ float g_deg[BATCH * NNODES];
__device__ int   g_rowG2[BATCH * NNODES];                      // sum of G2 per row
__device__ unsigned char g_Ah[(size_t)BATCH * NNODES * NNODES]; // G2>>8 (u8), 67MB
__device__ unsigned char g_Al[(size_t)BATCH * NNODES * NNODES]; // (G2&255)-128 (s8)
__device__ unsigned char g_zTh[(size_t)BATCH * DIM * NNODES];   // zq>>8 (s8), transposed
__device__ unsigned char g_zTl[(size_t)BATCH * DIM * NNODES];   // (zq&255)-128 (s8)
__device__ float g_zfA[TOTE];
__device__ float g_zfB[TOTE];
__device__ __align__(16) float g_part[KSPLIT][TOTE];
__device__ float g_h1[TOTE], g_h2[TOTE], g_h3[TOTE];
__device__ unsigned int g_zmaxbits[NLAYER + 1];
__device__ int g_colzq[NLAYER][BATCH][DIM];

// ---------------- helpers ----------------
__device__ __forceinline__ void cp_async16(void* smem_dst, const void* gmem_src) {
    unsigned s = (unsigned)__cvta_generic_to_shared(smem_dst);
    asm volatile("cp.async.cg.shared.global [%0], [%1], 16;\n" :: "r"(s), "l"(gmem_src));
}
__device__ __forceinline__ void cp_commit() { asm volatile("cp.async.commit_group;\n"); }
template<int NREM>
__device__ __forceinline__ void cp_wait() {
    asm volatile("cp.async.wait_group %0;\n" :: "n"(NREM));
}
__device__ __forceinline__ void imma_u8s8(int* c, const uint32_t* a, const uint32_t* b) {
    asm volatile(
        "mma.sync.aligned.m16n8k32.row.col.s32.u8.s8.s32 "
        "{%0,%1,%2,%3}, {%4,%5,%6,%7}, {%8,%9}, {%0,%1,%2,%3};"
        : "+r"(c[0]), "+r"(c[1]), "+r"(c[2]), "+r"(c[3])
        : "r"(a[0]), "r"(a[1]), "r"(a[2]), "r"(a[3]), "r"(b[0]), "r"(b[1]));
}
__device__ __forceinline__ void imma_s8s8(int* c, const uint32_t* a, const uint32_t* b) {
    asm volatile(
        "mma.sync.aligned.m16n8k32.row.col.s32.s8.s8.s32 "
        "{%0,%1,%2,%3}, {%4,%5,%6,%7}, {%8,%9}, {%0,%1,%2,%3};"
        : "+r"(c[0]), "+r"(c[1]), "+r"(c[2]), "+r"(c[3])
        : "r"(a[0]), "r"(a[1]), "r"(a[2]), "r"(a[3]), "r"(b[0]), "r"(b[1]));
}

// ---------------- 0) init: zero maxes + colsums ----------------
__global__ void init_kernel() {
    int t = threadIdx.x;
    if (t < NLAYER + 1) g_zmaxbits[t] = 0u;
    int* c = &g_colzq[0][0][0];
    for (int i = t; i < NLAYER * BATCH * DIM; i += 256) c[i] = 0;
}

// ---------------- 1) prep: degrees + G -> int8 planes + row sums (G read once) --
__global__ void prep_kernel(const float* __restrict__ graph) {
    const int row = blockIdx.x;                          // b*N + i
    const float4* src = (const float4*)(graph + (size_t)row * NNODES);
    uint32_t* dH = (uint32_t*)(g_Ah + (size_t)row * NNODES);
    uint32_t* dL = (uint32_t*)(g_Al + (size_t)row * NNODES);
    float sf = 0.f;
    int   si = 0;
    #pragma unroll
    for (int u = 0; u < NNODES / 4 / 256; u++) {
        const int idx = threadIdx.x + u * 256;
        float4 v = src[idx];
        sf += (v.x + v.y) + (v.z + v.w);
        uint32_t q0 = min(65535u, __float2uint_rn(v.x * 65536.f));
        uint32_t q1 = min(65535u, __float2uint_rn(v.y * 65536.f));
        uint32_t q2 = min(65535u, __float2uint_rn(v.z * 65536.f));
        uint32_t q3 = min(65535u, __float2uint_rn(v.w * 65536.f));
        si += (int)(q0 + q1 + q2 + q3);
        dH[idx] = (q0 >> 8) | ((q1 >> 8) << 8) | ((q2 >> 8) << 16) | ((q3 >> 8) << 24);
        dL[idx] = ((q0 & 255u) ^ 128u) | (((q1 & 255u) ^ 128u) << 8)
                | (((q2 & 255u) ^ 128u) << 16) | (((q3 & 255u) ^ 128u) << 24);
    }
    #pragma unroll
    for (int o = 16; o > 0; o >>= 1) {
        sf += __shfl_down_sync(0xffffffffu, sf, o);
        si += __shfl_down_sync(0xffffffffu, si, o);
    }
    __shared__ float rf[8];
    __shared__ int   ri[8];
    if ((threadIdx.x & 31) == 0) { rf[threadIdx.x >> 5] = sf; ri[threadIdx.x >> 5] = si; }
    __syncthreads();
    if (threadIdx.x == 0) {
        float tot = 1.0f; int ti = 0;
        #pragma unroll
        for (int w = 0; w < 8; w++) { tot += rf[w]; ti += ri[w]; }
        g_deg[row]   = 1.0f / (sqrtf(tot) + 1e-7f);
        g_rowG2[row] = ti;
    }
}

// ---------------- 2) z0 = D*x (f32) + running max ----------------
__global__ void scale0_kernel(const float* __restrict__ x) {
    const int i = blockIdx.x * 256 + threadIdx.x;        // f4 index
    float4 v = ((const float4*)x)[i];
    const float d = g_deg[i >> 4];
    float4 z = make_float4(v.x * d, v.y * d, v.z * d, v.w * d);
    ((float4*)g_zfA)[i] = z;
    float m = fmaxf(fmaxf(fabsf(z.x), fabsf(z.y)), fmaxf(fabsf(z.z), fabsf(z.w)));
    #pragma unroll
    for (int o = 16; o > 0; o >>= 1) m = fmaxf(m, __shfl_down_sync(0xffffffffu, m, o));
    __shared__ float rm[8];
    if ((threadIdx.x & 31) == 0) rm[threadIdx.x >> 5] = m;
    __syncthreads();
    if (threadIdx.x == 0) {
        float bm = rm[0];
        #pragma unroll
        for (int w = 1; w < 8; w++) bm = fmaxf(bm, rm[w]);
        atomicMax(&g_zmaxbits[0], __float_as_uint(bm));
    }
}

// ---------------- 3) quantize+transpose z -> int8 planes + colsums ----------------
__global__ void quantT_kernel(const float* __restrict__ zf, int layer) {
    __shared__ float tile[64][65];
    const int b = blockIdx.y, k0 = blockIdx.x * 64;
    const int tid = threadIdx.x;
    const float* Z = zf + (size_t)b * NNODES * DIM;
    {
        int r  = tid >> 2;
        int c0 = (tid & 3) * 16;
        #pragma unroll
        for (int j = 0; j < 4; j++) {
            float4 v = *(const float4*)&Z[(size_t)(k0 + r) * DIM + c0 + j * 4];
            tile[r][c0 + j * 4 + 0] = v.x;
            tile[r][c0 + j * 4 + 1] = v.y;
            tile[r][c0 + j * 4 + 2] = v.z;
            tile[r][c0 + j * 4 + 3] = v.w;
        }
    }
    __syncthreads();
    const float zm = __uint_as_float(g_zmaxbits[layer]);
    const float rs = zm > 0.f ? 32700.f / zm : 0.f;
    {
        const int n  = tid >> 2;
        const int kq = (tid & 3) * 16;
        int csum = 0;
        uint32_t hw[4], lw[4];
        #pragma unroll
        for (int j = 0; j < 4; j++) {
            uint32_t hword = 0, lword = 0;
            #pragma unroll
            for (int bb = 0; bb < 4; bb++) {
                int k = kq + j * 4 + bb;
                int q = __float2int_rn(tile[k][n] * rs);
                csum += q;
                hword |= (((uint32_t)(q >> 8)) & 255u) << (8 * bb);
                lword |= ((((uint32_t)q & 255u)) ^ 128u) << (8 * bb);
            }
            hw[j] = hword; lw[j] = lword;
        }
        size_t base = ((size_t)(b * DIM + n)) * NNODES + k0 + kq;
        #pragma unroll
        for (int j = 0; j < 4; j++) {
            *(uint32_t*)(g_zTh + base + j * 4) = hw[j];
            *(uint32_t*)(g_zTl + base + j * 4) = lw[j];
        }
        csum += __shfl_down_sync(0xffffffffu, csum, 2);
        csum += __shfl_down_sync(0xffffffffu, csum, 1);
        if ((tid & 3) == 0) atomicAdd(&g_colzq[layer][b][n], csum);
    }
}

// ---------------- 4) propagation partial GEMM (int8, 3 planes) ----------------
__global__ void __launch_bounds__(THREADS)
prop_kernel() {
    __shared__ __align__(16) unsigned char sAh[2][TM][48];
    __shared__ __align__(16) unsigned char sAl[2][TM][48];
    __shared__ __align__(16) unsigned char sBh[2][DIM][48];
    __shared__ __align__(16) unsigned char sBl[2][DIM][48];

    const int tid  = threadIdx.x;
    const int lane = tid & 31;
    const int wid  = tid >> 5;
    const int wm   = (wid >> 1) * 32;
    const int wn   = (wid & 1) * 32;
    const int r    = lane >> 2;
    const int kq4  = (lane & 3) * 4;

    const int b = blockIdx.z;
    const int rowBase = blockIdx.x * TM;
    const int slice = blockIdx.y;
    const size_t kbase = (size_t)slice * KLEN;
    const unsigned char* Ah = g_Ah + ((size_t)(b * NNODES + rowBase)) * NNODES;
    const unsigned char* Al = g_Al + ((size_t)(b * NNODES + rowBase)) * NNODES;
    const unsigned char* Th = g_zTh + (size_t)b * DIM * NNODES;
    const unsigned char* Tl = g_zTl + (size_t)b * DIM * NNODES;

    int acc_hh[2][4][4], acc_mid[2][4][4];
    #pragma unroll
    for (int i = 0; i < 2; i++)
        #pragma unroll
        for (int j = 0; j < 4; j++)
            #pragma unroll
            for (int k = 0; k < 4; k++) { acc_hh[i][j][k] = 0; acc_mid[i][j][k] = 0; }

    auto issue = [&](int t, int st) {
        const size_t k0 = kbase + (size_t)t * KT;
        const int m = tid >> 1, half = tid & 1;
        cp_async16(&sAh[st][m][half * 16], Ah + (size_t)m * NNODES + k0 + half * 16);
        cp_async16(&sAl[st][m][half * 16], Al + (size_t)m * NNODES + k0 + half * 16);
        cp_async16(&sBh[st][m][half * 16], Th + (size_t)m * NNODES + k0 + half * 16);
        cp_async16(&sBl[st][m][half * 16], Tl + (size_t)m * NNODES + k0 + half * 16);
        cp_commit();
    };

    issue(0, 0);
    issue(1, 1);

    for (int t = 0; t < NTL; t++) {
        const int st = t & 1;
        if (t + 1 < NTL) cp_wait<1>(); else cp_wait<0>();
        __syncthreads();

        uint32_t ah[2][4], al[2][4];
        #pragma unroll
        for (int mb = 0; mb < 2; mb++) {
            const int m0 = wm + mb * 16 + r;
            ah[mb][0] = *(const uint32_t*)&sAh[st][m0    ][kq4];
            ah[mb][1] = *(const uint32_t*)&sAh[st][m0 + 8][kq4];
            ah[mb][2] = *(const uint32_t*)&sAh[st][m0    ][kq4 + 16];
            ah[mb][3] = *(const uint32_t*)&sAh[st][m0 + 8][kq4 + 16];
            al[mb][0] = *(const uint32_t*)&sAl[st][m0    ][kq4];
            al[mb][1] = *(const uint32_t*)&sAl[st][m0 + 8][kq4];
            al[mb][2] = *(const uint32_t*)&sAl[st][m0    ][kq4 + 16];
            al[mb][3] = *(const uint32_t*)&sAl[st][m0 + 8][kq4 + 16];
        }
        uint32_t bh[4][2], bl[4][2];
        #pragma unroll
        for (int nb = 0; nb < 4; nb++) {
            const int n = wn + nb * 8 + r;
            bh[nb][0] = *(const uint32_t*)&sBh[st][n][kq4];
            bh[nb][1] = *(const uint32_t*)&sBh[st][n][kq4 + 16];
            bl[nb][0] = *(const uint32_t*)&sBl[st][n][kq4];
            bl[nb][1] = *(const uint32_t*)&sBl[st][n][kq4 + 16];
        }
        #pragma unroll
        for (int mb = 0; mb < 2; mb++)
            #pragma unroll
            for (int nb = 0; nb < 4; nb++) {
                imma_u8s8(acc_hh [mb][nb], ah[mb], bh[nb]);
                imma_u8s8(acc_mid[mb][nb], ah[mb], bl[nb]);
                imma_s8s8(acc_mid[mb][nb], al[mb], bh[nb]);
            }
        __syncthreads();
        if (t + 2 < NTL) issue(t + 2, st);
    }

    // write partial (int units): P = 65536*S_hh + 256*S_mid
    float* P = g_part[slice] + (size_t)b * NNODES * DIM;
    #pragma unroll
    for (int mb = 0; mb < 2; mb++) {
        const int r0 = rowBase + wm + mb * 16 + r;
        const int r1 = r0 + 8;
        #pragma unroll
        for (int nb = 0; nb < 4; nb++) {
            const int c = wn + nb * 8 + 2 * (lane & 3);
            float p0 = (float)((double)acc_hh[mb][nb][0] * 65536.0 + (double)acc_mid[mb][nb][0] * 256.0);
            float p1 = (float)((double)acc_hh[mb][nb][1] * 65536.0 + (double)acc_mid[mb][nb][1] * 256.0);
            float p2 = (float)((double)acc_hh[mb][nb][2] * 65536.0 + (double)acc_mid[mb][nb][2] * 256.0);
            float p3 = (float)((double)acc_hh[mb][nb][3] * 65536.0 + (double)acc_mid[mb][nb][3] * 256.0);
            *(float2*)&P[(size_t)r0 * DIM + c] = make_float2(p0, p1);
            *(float2*)&P[(size_t)r1 * DIM + c] = make_float2(p2, p3);
        }
    }
}

// ---------------- 5) combine: h = d*(scale*(S+corr) + z_prev); z_next; max -----
__global__ void combine_kernel(const float* __restrict__ zfIn,
                               float* __restrict__ hOut, float* __restrict__ zfOut,
                               int layer) {
    const int i = blockIdx.x * 256 + threadIdx.x;        // f4 index
    const int node = i >> 4;
    const int b = node >> 12;
    const int n4 = (i & 15) * 4;
    const float d = g_deg[node];

    float4 s = ((const float4*)g_part[0])[i];
    #pragma unroll
    for (int p = 1; p < KSPLIT; p++) {
        float4 sp = ((const float4*)g_part[p])[i];
        s.x += sp.x; s.y += sp.y; s.z += sp.z; s.w += sp.w;
    }

    const float zm = __uint_as_float(g_zmaxbits[layer]);
    const float sc = zm > 0.f ? (zm / 32700.f) * (1.f / 65536.f) : 0.f;
    const float rg = (float)g_rowG2[node];
    int4 cq = *(const int4*)&g_colzq[layer][b][n4];
    const float CK = 16384.f * 4096.f;
    float c0 = 128.f * (rg + (float)cq.x) - CK;
    float c1 = 128.f * (rg + (float)cq.y) - CK;
    float c2 = 128.f * (rg + (float)cq.z) - CK;
    float c3 = 128.f * (rg + (float)cq.w) - CK;

    float4 zp = ((const float4*)zfIn)[i];
    float4 h;
    h.x = d * (sc * (s.x + c0) + zp.x);
    h.y = d * (sc * (s.y + c1) + zp.y);
    h.z = d * (sc * (s.z + c2) + zp.z);
    h.w = d * (sc * (s.w + c3) + zp.w);
    ((float4*)hOut)[i] = h;

    float4 zn = make_float4(d * h.x, d * h.y, d * h.z, d * h.w);
    ((float4*)zfOut)[i] = zn;

    float m = fmaxf(fmaxf(fabsf(zn.x), fabsf(zn.y)), fmaxf(fabsf(zn.z), fabsf(zn.w)));
    #pragma unroll
    for (int o = 16; o > 0; o >>= 1) m = fmaxf(m, __shfl_down_sync(0xffffffffu, m, o));
    __shared__ float rm[8];
    if ((threadIdx.x & 31) == 0) rm[threadIdx.x >> 5] = m;
    __syncthreads();
    if (threadIdx.x == 0) {
        float bm = rm[0];
        #pragma unroll
        for (int w = 1; w < 8; w++) bm = fmaxf(bm, rm[w]);
        atomicMax(&g_zmaxbits[layer + 1], __float_as_uint(bm));
    }
}

// ---------------- 6) out = concat(x,h1,h2,h3) @ W^T + b ----------------
__global__ void __launch_bounds__(256)
out_gemm_kernel(const float* __restrict__ x,
                const float* __restrict__ W,
                const float* __restrict__ bias,
                float* __restrict__ out)
{
    __shared__ float catS[16][256];
    __shared__ float Wt[64][65];

    const int tid = threadIdx.x;
    const int rowBase = blockIdx.x * 16;

    const float* srcs[4] = { x, g_h1, g_h2, g_h3 };
    {
        int r = tid >> 4, f4 = tid & 15;
        #pragma unroll
        for (int s = 0; s < 4; s++) {
            float4 v = *(const float4*)&srcs[s][(size_t)(rowBase + r) * DIM + f4 * 4];
            *(float4*)&catS[r][s * 64 + f4 * 4] = v;
        }
    }

    const int o  = tid & 63;
    const int rg = tid >> 6;

    float acc[4];
    {
        float bv = bias[o];
        #pragma unroll
        for (int j = 0; j < 4; j++) acc[j] = bv;
    }

    for (int fc = 0; fc < 4; fc++) {
        __syncthreads();
        #pragma unroll
        for (int u = 0; u < 4; u++) {
            int i  = tid + u * 256;
            int ro = i >> 4;
            int f4 = i & 15;
            float4 v = *(const float4*)&W[(size_t)ro * 256 + fc * 64 + f4 * 4];
            Wt[f4 * 4 + 0][ro] = v.x;
            Wt[f4 * 4 + 1][ro] = v.y;
            Wt[f4 * 4 + 2][ro] = v.z;
            Wt[f4 * 4 + 3][ro] = v.w;
        }
        __syncthreads();
        #pragma unroll
        for (int fl = 0; fl < 64; fl++) {
            float w = Wt[fl][o];
            #pragma unroll
            for (int j = 0; j < 4; j++)
                acc[j] += catS[rg * 4 + j][fc * 64 + fl] * w;
        }
    }

    #pragma unroll
    for (int j = 0; j < 4; j++)
        out[(size_t)(rowBase + rg * 4 + j) * DIM + o] = acc[j];
}

// ---------------- launch ----------------
template<typename T>
static T* symAddr(const T& symbol) {
    void* p = nullptr;
    cudaGetSymbolAddress(&p, symbol);
    return (T*)p;
}

extern "C" void kernel_launch(void* const* d_in, const int* in_sizes, int n_in,
                              void* d_out, int out_size) {
    const float* x     = (const float*)d_in[0];
    const float* graph = (const float*)d_in[1];
    const float* W     = (const float*)d_in[2];
    const float* bias  = (const float*)d_in[3];
    float* out = (float*)d_out;

    float* zfA = (float*)symAddr(g_zfA);
    float* zfB = (float*)symAddr(g_zfB);
    float* h1  = (float*)symAddr(g_h1);
    float* h2  = (float*)symAddr(g_h2);
    float* h3  = (float*)symAddr(g_h3);

    init_kernel<<<1, 256>>>();
    prep_kernel<<<BATCH * NNODES, 256>>>(graph);
    scale0_kernel<<<TOTE / 4 / 256, 256>>>(x);

    const dim3 qg(NNODES / 64, BATCH);
    const dim3 pg(NNODES / TM, KSPLIT, BATCH);
    const int cb = TOTE / 4 / 256;

    quantT_kernel<<<qg, 256>>>(zfA, 0);
    prop_kernel<<<pg, THREADS>>>();
    combine_kernel<<<cb, 256>>>(zfA, h1, zfB, 0);

    quantT_kernel<<<qg, 256>>>(zfB, 1);
    prop_kernel<<<pg, THREADS>>>();
    combine_kernel<<<cb, 256>>>(zfB, h2, zfA, 1);

    quantT_kernel<<<qg, 256>>>(zfA, 2);
    prop_kernel<<<pg, THREADS>>>();
    combine_kernel<<<cb, 256>>>(zfA, h3, zfB, 2);

    out_gemm_kernel<<<(BATCH * NNODES) / 16, 256>>>(x, W, bias, out);
}